// round 7
// baseline (speedup 1.0000x reference)
#include <cuda_runtime.h>
#include <cuda_bf16.h>
#include <cstdint>
#include <math.h>

#define DDIM   256
#define NROWS  8192
#define TMT    128            // tile M
#define TNT    128            // tile N
#define KC     64             // bf16 per K-chunk (128 bytes per smem row)
#define NCHUNK (DDIM / KC)    // 4
#define TILE_B 16384          // 128 rows x 128 bytes
#define SMEM_DYN (2 * 2 * TILE_B)   // 2 stages x {A, B} = 64 KB
#define NCOLBLK 64

// ---------------- device scratch (no allocation allowed) -------------------
__device__ double g_part[NCOLBLK][DDIM];   // per-block column partial sums
__device__ float  g_sq[NROWS];
__device__ float  g_inv4;                  // log2(e) / (bw*16)
__device__ double g_acc;
__device__ unsigned g_tick_cs;
__device__ unsigned g_tick_mm;
__device__ __nv_bfloat16 g_bf[(size_t)NROWS * DDIM];

// ---------------- PTX helpers (base sm_80-class, legal on sm_103) ----------
__device__ __forceinline__ uint32_t smem_u32(const void* p) {
    uint32_t a;
    asm("{ .reg .u64 t; cvta.to.shared.u64 t, %1; cvt.u32.u64 %0, t; }"
        : "=r"(a) : "l"(p));
    return a;
}
__device__ __forceinline__ void ldsm4(uint32_t* r, uint32_t addr) {
    asm volatile("ldmatrix.sync.aligned.m8n8.x4.shared.b16 {%0,%1,%2,%3}, [%4];"
                 : "=r"(r[0]), "=r"(r[1]), "=r"(r[2]), "=r"(r[3]) : "r"(addr));
}
__device__ __forceinline__ void mma16816(float* c, const uint32_t* a,
                                         uint32_t b0, uint32_t b1) {
    asm volatile(
        "mma.sync.aligned.m16n8k16.row.col.f32.bf16.bf16.f32 "
        "{%0,%1,%2,%3}, {%4,%5,%6,%7}, {%8,%9}, {%0,%1,%2,%3};"
        : "+f"(c[0]), "+f"(c[1]), "+f"(c[2]), "+f"(c[3])
        : "r"(a[0]), "r"(a[1]), "r"(a[2]), "r"(a[3]), "r"(b0), "r"(b1));
}
__device__ __forceinline__ void cp16(uint32_t dst, const void* src) {
    asm volatile("cp.async.cg.shared.global [%0], [%1], 16;"
                 :: "r"(dst), "l"(__cvta_generic_to_global(src)) : "memory");
}
__device__ __forceinline__ float ex2f(float x) {
    float r;
    asm("ex2.approx.ftz.f32 %0, %1;" : "=f"(r) : "f"(x));
    return r;
}

// ---------------- prep: squared norms + bf16 round (no atomics) -------------
__global__ void k_prep(const float* __restrict__ src,
                       const float* __restrict__ tgt, int n) {
    if (blockIdx.x == 0 && threadIdx.x == 0) g_tick_cs = 0u;
    int row  = blockIdx.x * 8 + (threadIdx.x >> 5);
    int lane = threadIdx.x & 31;
    const float* p = (row < n) ? (src + (size_t)row * DDIM)
                               : (tgt + (size_t)(row - n) * DDIM);
    const float4* p4 = (const float4*)p;
    float s = 0.f;
#pragma unroll
    for (int i = 0; i < 2; ++i) {
        float4 v = p4[lane + i * 32];
        s += v.x * v.x + v.y * v.y + v.z * v.z + v.w * v.w;
        __nv_bfloat162 b01 = __floats2bfloat162_rn(v.x, v.y);
        __nv_bfloat162 b23 = __floats2bfloat162_rn(v.z, v.w);
        size_t e0 = (size_t)row * DDIM + (lane + i * 32) * 4;
        __nv_bfloat162* H = (__nv_bfloat162*)(g_bf + e0);
        H[0] = b01; H[1] = b23;
    }
#pragma unroll
    for (int o = 16; o; o >>= 1) s += __shfl_xor_sync(0xffffffffu, s, o);
    if (lane == 0) g_sq[row] = s;
}

// ---------------- colsum partials + (last block) bandwidth ------------------
// sum(L2) = 2*N*S - 2*||colsum||^2 ; bw = sum/(N^2-N)/4 ; inv4 = log2e/(bw*16)
__global__ void k_colsum(const float* __restrict__ src,
                         const float* __restrict__ tgt, int n) {
    __shared__ double sh[DDIM];
    __shared__ bool s_last;
    int col = threadIdx.x;
    int r0  = blockIdx.x * 128;
    double s = 0.0;
    for (int r = r0; r < r0 + 128; ++r) {
        const float* p = (r < n) ? (src + (size_t)r * DDIM)
                                 : (tgt + (size_t)(r - n) * DDIM);
        s += (double)p[col];
    }
    g_part[blockIdx.x][col] = s;
    __threadfence();
    __syncthreads();
    if (col == 0)
        s_last = (atomicAdd(&g_tick_cs, 1u) == (unsigned)(gridDim.x - 1));
    __syncthreads();
    if (!s_last) return;

    // last block: reduce partials -> colsum_c, then ||colsum||^2 and S
    double cs = 0.0;
#pragma unroll
    for (int b = 0; b < NCOLBLK; ++b) cs += g_part[b][col];
    sh[col] = cs * cs;
    __syncthreads();
    for (int o = DDIM / 2; o; o >>= 1) {
        if (col < o) sh[col] += sh[col + o];
        __syncthreads();
    }
    double csq = sh[0];
    __syncthreads();
    double Sp = 0.0;
#pragma unroll
    for (int k = 0; k < NROWS / DDIM; ++k) Sp += (double)g_sq[col + k * DDIM];
    sh[col] = Sp;
    __syncthreads();
    for (int o = DDIM / 2; o; o >>= 1) {
        if (col < o) sh[col] += sh[col + o];
        __syncthreads();
    }
    if (col == 0) {
        double N = 2.0 * (double)n;
        double sumL2 = 2.0 * N * sh[0] - 2.0 * csq;
        double bw = sumL2 / (N * N - N) / 4.0;
        g_inv4 = (float)(1.4426950408889634 / (bw * 16.0));
        g_acc = 0.0;
        g_tick_mm = 0u;
    }
}

// ---------------- main fused mma.sync kernel ---------------------------------
// Smem tile layout: 128 rows x 128B, 16B granule g stored at g ^ (row & 7).
__device__ __forceinline__ void copy_chunk(int c, uint32_t sbuf,
                                           int row0, int col0, int tid) {
    int bases[2] = { row0, col0 };
#pragma unroll
    for (int t = 0; t < 2; ++t) {
        int R0 = bases[t];
        uint32_t tb = sbuf + t * TILE_B;
#pragma unroll
        for (int i = 0; i < 4; ++i) {
            int idx  = i * 256 + tid;      // 0..1023 granules
            int r    = idx >> 3;
            int gcol = idx & 7;
            const void* gp = g_bf + (size_t)(R0 + r) * DDIM + c * KC + gcol * 8;
            uint32_t soff = tb + r * 128 + (((uint32_t)(gcol ^ (r & 7))) << 4);
            cp16(soff, gp);
        }
    }
}

__device__ __forceinline__ void compute_chunk(
    uint32_t sbuf, float acc[2][8][4],
    const uint32_t aRow[2], const uint32_t bRow[4], int rs, int gb) {
#pragma unroll
    for (int ks = 0; ks < 4; ++ks) {
        int g = ks * 2 + gb;
        uint32_t swz = (uint32_t)(g ^ rs) << 4;
        uint32_t A[2][4], Bm[4][4];
#pragma unroll
        for (int mi = 0; mi < 2; ++mi)
            ldsm4(A[mi], sbuf + 0 * TILE_B + aRow[mi] + swz);
#pragma unroll
        for (int q = 0; q < 4; ++q)
            ldsm4(Bm[q], sbuf + 1 * TILE_B + bRow[q] + swz);
#pragma unroll
        for (int mi = 0; mi < 2; ++mi)
#pragma unroll
            for (int q = 0; q < 4; ++q) {
                mma16816(acc[mi][2 * q + 0], A[mi], Bm[q][0], Bm[q][2]);
                mma16816(acc[mi][2 * q + 1], A[mi], Bm[q][1], Bm[q][3]);
            }
    }
}

__global__ void __launch_bounds__(256, 2)
k_main(int n, int nTiles, int extra, float* out) {
    extern __shared__ __align__(128) char smem[];
    uint32_t sb = smem_u32(smem);
    __shared__ float s_sqi[128], s_sqj[128], red[256];

    const int tid  = threadIdx.x;
    const int lane = tid & 31;
    const int w    = tid >> 5;
    const int wm   = w & 3;        // 4 row groups of 32
    const int wn   = w >> 2;       // 2 col groups of 64
    const int gid  = lane >> 2;
    const int tig  = lane & 3;
    const int l16  = lane & 15;
    const int gb   = lane >> 4;
    const int rs   = l16 & 7;
    const float inv4 = g_inv4;

    const int myTiles = ((int)blockIdx.x < extra) ? 2 : 1;
    for (int tt = 0; tt < myTiles; ++tt) {
        int L = (tt == 0) ? (int)blockIdx.x : (int)(gridDim.x + blockIdx.x);

        // triangle decode
        int tj = (int)((sqrtf(8.0f * (float)L + 1.0f) - 1.0f) * 0.5f);
        while ((tj + 1) * (tj + 2) / 2 <= L) ++tj;
        while (tj * (tj + 1) / 2 > L) --tj;
        int ti = L - tj * (tj + 1) / 2;
        const int row0 = ti * TMT;
        const int col0 = tj * TNT;

        __syncthreads();   // previous tile's epilogue fully done with smem
        if (tid < 128) {
            s_sqi[tid] = g_sq[row0 + tid];
            s_sqj[tid] = g_sq[col0 + tid];
        }

        uint32_t aRow[2], bRow[4];
#pragma unroll
        for (int mi = 0; mi < 2; ++mi)
            aRow[mi] = (uint32_t)(wm * 32 + mi * 16 + l16) * 128u;
#pragma unroll
        for (int q = 0; q < 4; ++q)
            bRow[q] = (uint32_t)(wn * 64 + q * 16 + l16) * 128u;

        float acc[2][8][4];
#pragma unroll
        for (int mi = 0; mi < 2; ++mi)
#pragma unroll
            for (int nj = 0; nj < 8; ++nj)
#pragma unroll
                for (int e = 0; e < 4; ++e) acc[mi][nj][e] = 0.f;

        copy_chunk(0, sb, row0, col0, tid);
        asm volatile("cp.async.commit_group;" ::: "memory");

#pragma unroll
        for (int c = 0; c < NCHUNK; ++c) {
            if (c + 1 < NCHUNK) {
                copy_chunk(c + 1, sb + ((c + 1) & 1) * (2 * TILE_B),
                           row0, col0, tid);
                asm volatile("cp.async.commit_group;" ::: "memory");
                asm volatile("cp.async.wait_group 1;" ::: "memory");
            } else {
                asm volatile("cp.async.wait_group 0;" ::: "memory");
            }
            __syncthreads();
            compute_chunk(sb + (c & 1) * (2 * TILE_B), acc, aRow, bRow, rs, gb);
            __syncthreads();
        }

        // ---- epilogue ----
        float sqi_r[4];
#pragma unroll
        for (int h = 0; h < 4; ++h) sqi_r[h] = s_sqi[wm * 32 + gid + h * 8];

        float tsum = 0.f;
#pragma unroll
        for (int mi = 0; mi < 2; ++mi) {
#pragma unroll
            for (int nj = 0; nj < 8; ++nj) {
                int cb = wn * 64 + nj * 8 + tig * 2;
                float sj0 = s_sqj[cb], sj1 = s_sqj[cb + 1];
#pragma unroll
                for (int e = 0; e < 4; ++e) {
                    float si = sqi_r[mi * 2 + (e >> 1)];
                    float sj = (e & 1) ? sj1 : sj0;
                    float l2 = fmaxf(si + sj - 2.f * acc[mi][nj][e], 0.f);
                    float ee = ex2f(-l2 * inv4);
                    float s  = ee;         // bw*16
                    ee *= ee; s += ee;     // bw*8
                    ee *= ee; s += ee;     // bw*4
                    ee *= ee; s += ee;     // bw*2
                    ee *= ee; s += ee;     // bw
                    tsum += s;
                }
            }
        }

        red[tid] = tsum;
        __syncthreads();
        if (tid < 128) red[tid] += red[tid + 128];
        __syncthreads();
        if (tid < 64) red[tid] += red[tid + 64];
        __syncthreads();
        if (tid < 32) {
            float v = red[tid] + red[tid + 32];
#pragma unroll
            for (int o = 16; o; o >>= 1) v += __shfl_xor_sync(0xffffffffu, v, o);
            if (tid == 0) {
                int half = n / TMT;
                double wgt = (ti == tj) ? 1.0
                           : (((ti < half) == (tj < half)) ? 2.0 : -2.0);
                atomicAdd(&g_acc, wgt * (double)v);
            }
        }
    }

    // ---- last finishing block writes the final scalar ----
    if (tid == 0) {
        __threadfence();
        unsigned old = atomicAdd(&g_tick_mm, 1u);
        if (old == (unsigned)(gridDim.x - 1)) {
            double total = atomicAdd(&g_acc, 0.0);  // coherent read
            out[0] = (float)(total / ((double)n * (double)n));
        }
    }
}

// ---------------------------------------------------------------------------
extern "C" void kernel_launch(void* const* d_in, const int* in_sizes, int n_in,
                              void* d_out, int out_size) {
    const float* src = (const float*)d_in[0];
    const float* tgt = (const float*)d_in[1];
    float* out = (float*)d_out;

    int n  = in_sizes[0] / DDIM;   // 4096
    int nt = 2 * n;                // 8192

    cudaFuncSetAttribute(k_main, cudaFuncAttributeMaxDynamicSharedMemorySize,
                         SMEM_DYN);

    k_prep<<<nt / 8, 256>>>(src, tgt, n);
    k_colsum<<<nt / 128, DDIM>>>(src, tgt, n);

    int numTiles = nt / TMT;                       // 64
    int T = numTiles * (numTiles + 1) / 2;         // 2080
    const int slots = 148 * 2;                     // SMs x CTAs/SM
    int G = (T / slots) * slots;                   // 2072
    if (G == 0) G = T;
    int extra = T - G;                             // 8 (blocks doing 2 tiles)
    k_main<<<G, 256, SMEM_DYN>>>(n, T, extra, out);
}